// round 14
// baseline (speedup 1.0000x reference)
#include <cuda_runtime.h>
#include <math.h>

#define T_ 256
#define N_ 64
#define C_ 4096
#define L_ 32
#define S_ 65           // 2*L+1
#define BLANK_ 0
#define LOG2E 1.4426950408889634f
#define LN2   0.6931471805599453f

#define TP_ (T_ + 16)   // padded T (fwd burst prefetch reaches row 144 max)

// Scratch, layout [n][t][s]: LINEAR probabilities of the 65 extended labels.
__device__ __align__(16) float g_p_ext[N_ * TP_ * S_ + 128];
__device__ float g_per_n[N_];
__device__ unsigned g_blkdone;   // zero-init; reset by last block each run

__device__ __forceinline__ float ex2(float x) {
    float y; asm("ex2.approx.ftz.f32 %0, %1;" : "=f"(y) : "f"(x)); return y;
}
__device__ __forceinline__ float lg2(float x) {
    float y; asm("lg2.approx.ftz.f32 %0, %1;" : "=f"(y) : "f"(x)); return y;
}
__device__ __forceinline__ float ldcg_f(const float* p) {
    float v; asm volatile("ld.global.cg.f32 %0, [%1];" : "=f"(v) : "l"(p)); return v;
}
__device__ __forceinline__ unsigned redux_max_u32(unsigned v) {
    unsigned r;
    asm volatile("redux.sync.max.u32 %0, %1, 0xffffffff;" : "=r"(r) : "r"(v));
    return r;
}

// skip flag for extended state s of batch n: odd s >= 3 with label != prev label
__device__ __forceinline__ bool skip_at(const int* __restrict__ targets, int n, int s) {
    if (s < S_ && (s & 1) && s >= 2) {
        int lab  = targets[n * L_ + (s >> 1)];
        int lab2 = targets[n * L_ + (s >> 1) - 1];
        return (lab != BLANK_) && (lab != lab2);
    }
    return false;
}

// Kernel 1: per (t,n) row of 4096 -> logsumexp -> gather 65 extended-label
// LINEAR probabilities into g_p_ext[n][t][s]. preds read with .cs (streaming).
// At HBM roofline (~32us).
__global__ void __launch_bounds__(256) lse_gather_kernel(
    const float* __restrict__ preds, const int* __restrict__ targets)
{
    const unsigned FULL = 0xffffffffu;
    const int row = blockIdx.x;        // row = t*N + n  (preds is (T,N,C))
    const int t   = row / N_;
    const int n   = row % N_;
    const float* __restrict__ p = preds + (size_t)row * C_;
    const int tid = threadIdx.x;

    float v[16];
    const float4* __restrict__ p4 = (const float4*)p;
    #pragma unroll
    for (int k = 0; k < 4; k++) {
        float4 f = __ldcs(p4 + tid + k * 256);     // ld.global.cs.v4.f32
        v[k*4+0] = f.x; v[k*4+1] = f.y; v[k*4+2] = f.z; v[k*4+3] = f.w;
    }

    float m = v[0];
    #pragma unroll
    for (int i = 1; i < 16; i++) m = fmaxf(m, v[i]);
    #pragma unroll
    for (int o = 16; o > 0; o >>= 1) m = fmaxf(m, __shfl_xor_sync(FULL, m, o));
    __shared__ float sm[8];
    if ((tid & 31) == 0) sm[tid >> 5] = m;
    __syncthreads();
    float bm = sm[0];
    #pragma unroll
    for (int i = 1; i < 8; i++) bm = fmaxf(bm, sm[i]);
    __syncthreads();

    const float bmL = bm * LOG2E;
    float s = 0.0f;
    #pragma unroll
    for (int i = 0; i < 16; i++) s += ex2(fmaf(v[i], LOG2E, -bmL));
    #pragma unroll
    for (int o = 16; o > 0; o >>= 1) s += __shfl_xor_sync(FULL, s, o);
    if ((tid & 31) == 0) sm[tid >> 5] = s;
    __syncthreads();
    float bs = sm[0];
    #pragma unroll
    for (int i = 1; i < 8; i++) bs += sm[i];

    const float lse = bm + lg2(bs) * LN2;

    if (tid < S_) {
        int label = (tid & 1) ? targets[n * L_ + (tid >> 1)] : BLANK_;
        g_p_ext[(n * TP_ + t) * S_ + tid] = ex2((p[label] - lse) * LOG2E);
    }
}

// Kernel 2: fwd/bwd split CTC recursion (linear domain, exponent-tracked).
// One block per batch n, 64 threads: warp 0 FORWARD (t=1..127), warp 1
// BACKWARD (t=255..128). Loads are double-buffered 8-row BURSTS so a
// consume never waits on a scoreboard slot rewritten by recent loads.
// Recursion arithmetic identical to the round-7/12/13 kernels (rel 1.4e-6).
__global__ void __launch_bounds__(64) ctc_forward_kernel(
    const int* __restrict__ targets,
    const int* __restrict__ pred_lengths,
    const int* __restrict__ target_lengths,
    float*     __restrict__ out)
{
    const unsigned FULL = 0xffffffffu;
    const int tid  = threadIdx.x;
    const int warp = tid >> 5;
    const int lane = tid & 31;
    const bool fwd = (warp == 0);
    const int n    = blockIdx.x;

    const int tl = target_lengths[n];
    const int pl = pred_lengths[n];
    const int Sv = 2 * tl + 1;
    const int s0 = 3 * lane;

    __shared__ float sA[96];
    __shared__ float sG[96];
    __shared__ int   sE[2];             // [0]=E_fwd, [1]=E_bwd

    bool valid[3];
    #pragma unroll
    for (int j = 0; j < 3; j++) valid[j] = ((s0 + j) < S_) && ((s0 + j) < Sv);

    const float* __restrict__ pn = g_p_ext + n * (TP_ * S_);
    float a[3];
    int E = 0;
    float lp[2][8][3];                  // double-buffered 8-row chunks

    if (fwd) {
        bool skip[3];
        #pragma unroll
        for (int j = 0; j < 3; j++) skip[j] = skip_at(targets, n, s0 + j);

        // alpha0
        {
            float p0 = pn[0], p1 = pn[1];
            #pragma unroll
            for (int j = 0; j < 3; j++) {
                int s = s0 + j;
                float a0 = 0.0f;
                if (s == 0) a0 = p0;
                if (s == 1 && tl > 0) a0 = p1;
                a[j] = valid[j] ? a0 : 0.0f;
            }
        }

        // preload: buf0 <- rows 1..8, buf1 <- rows 9..16 (two bursts)
        #pragma unroll
        for (int k = 0; k < 8; k++) {
            const float* r = pn + (1 + k) * S_ + s0;
            lp[0][k][0] = r[0]; lp[0][k][1] = r[1]; lp[0][k][2] = r[2];
        }
        #pragma unroll
        for (int k = 0; k < 8; k++) {
            const float* r = pn + (9 + k) * S_ + s0;
            lp[1][k][0] = r[0]; lp[1][k][1] = r[1]; lp[1][k][2] = r[2];
        }

        #pragma unroll 2
        for (int b = 0; b < 16; b++) {
            const int buf = b & 1;
            // consume rows t = 8b+1 .. 8b+8
            #pragma unroll
            for (int k = 0; k < 8; k++) {
                const int t = 8 * b + 1 + k;
                float l0 = lp[buf][k][0], l1 = lp[buf][k][1], l2 = lp[buf][k][2];

                float nb1 = __shfl_up_sync(FULL, a[1], 1);   // state s0-2
                float nb2 = __shfl_up_sync(FULL, a[2], 1);   // state s0-1
                if (lane == 0) { nb1 = 0.0f; nb2 = 0.0f; }

                float c0 = a[0] + nb2  + (skip[0] ? nb1  : 0.0f);
                float c1 = a[1] + a[0] + (skip[1] ? nb2  : 0.0f);
                float c2 = a[2] + a[1] + (skip[2] ? a[0] : 0.0f);

                if (t < 128 && t < pl) {      // apply steps 1..127 only
                    a[0] = valid[0] ? (c0 * l0) : 0.0f;
                    a[1] = valid[1] ? (c1 * l1) : 0.0f;
                    a[2] = valid[2] ? (c2 * l2) : 0.0f;
                }

                if ((t & 3) == 0) {
                    float mx = fmaxf(fmaxf(a[0], a[1]), a[2]);
                    unsigned mb = redux_max_u32(__float_as_uint(mx));
                    if (mb >= 0x00800000u) {
                        int e = (int)(mb >> 23) - 127;
                        float sc = __uint_as_float((unsigned)(127 - e) << 23);
                        a[0] *= sc; a[1] *= sc; a[2] *= sc;
                        E += e;
                    }
                }
            }
            // refill drained buffer with rows 8(b+2)+1 .. 8(b+2)+8 (max 144 < TP_)
            #pragma unroll
            for (int k = 0; k < 8; k++) {
                const float* r = pn + (8 * (b + 2) + 1 + k) * S_ + s0;
                lp[buf][k][0] = r[0]; lp[buf][k][1] = r[1]; lp[buf][k][2] = r[2];
            }
        }
        sA[s0] = a[0]; sA[s0 + 1] = a[1]; sA[s0 + 2] = a[2];
        if (lane == 0) sE[0] = E;
    } else {
        bool sk2 = skip_at(targets, n, s0 + 2);
        bool sk3 = skip_at(targets, n, s0 + 3);
        bool sk4 = skip_at(targets, n, s0 + 4);

        // g init = endpoint indicator
        const int end = 2 * tl;
        #pragma unroll
        for (int j = 0; j < 3; j++) {
            int s = s0 + j;
            float g0 = 0.0f;
            if (s == end) g0 = 1.0f;
            if (tl > 0 && s == end - 1) g0 = 1.0f;
            a[j] = valid[j] ? g0 : 0.0f;
        }

        // preload: buf0 <- rows 255..248, buf1 <- rows 247..240
        #pragma unroll
        for (int k = 0; k < 8; k++) {
            const float* r = pn + (255 - k) * S_ + s0;
            lp[0][k][0] = r[0]; lp[0][k][1] = r[1]; lp[0][k][2] = r[2];
        }
        #pragma unroll
        for (int k = 0; k < 8; k++) {
            const float* r = pn + (247 - k) * S_ + s0;
            lp[1][k][0] = r[0]; lp[1][k][1] = r[1]; lp[1][k][2] = r[2];
        }

        #pragma unroll 2
        for (int b = 0; b < 16; b++) {
            const int buf = b & 1;
            // consume rows t = 255-8b .. 248-8b
            #pragma unroll
            for (int k = 0; k < 8; k++) {
                const int td = 8 * b + k;
                const int t  = 255 - td;
                float l0 = lp[buf][k][0], l1 = lp[buf][k][1], l2 = lp[buf][k][2];

                float h0 = a[0] * l0;
                float h1 = a[1] * l1;
                float h2 = a[2] * l2;
                float hd0 = __shfl_down_sync(FULL, h0, 1);   // state s0+3
                float hd1 = __shfl_down_sync(FULL, h1, 1);   // state s0+4
                if (lane == 31) { hd0 = 0.0f; hd1 = 0.0f; }

                if (t < pl) {
                    a[0] = valid[0] ? (h0 + h1  + (sk2 ? h2  : 0.0f)) : 0.0f;
                    a[1] = valid[1] ? (h1 + h2  + (sk3 ? hd0 : 0.0f)) : 0.0f;
                    a[2] = valid[2] ? (h2 + hd0 + (sk4 ? hd1 : 0.0f)) : 0.0f;
                }

                if ((td & 3) == 3) {
                    float mx = fmaxf(fmaxf(a[0], a[1]), a[2]);
                    unsigned mb = redux_max_u32(__float_as_uint(mx));
                    if (mb >= 0x00800000u) {
                        int e = (int)(mb >> 23) - 127;
                        float sc = __uint_as_float((unsigned)(127 - e) << 23);
                        a[0] *= sc; a[1] *= sc; a[2] *= sc;
                        E += e;
                    }
                }
            }
            // refill drained buffer with rows 255-8(b+2) .. 248-8(b+2) (min 112)
            #pragma unroll
            for (int k = 0; k < 8; k++) {
                const float* r = pn + (255 - 8 * (b + 2) - k) * S_ + s0;
                lp[buf][k][0] = r[0]; lp[buf][k][1] = r[1]; lp[buf][k][2] = r[2];
            }
        }
        sG[s0] = a[0]; sG[s0 + 1] = a[1]; sG[s0 + 2] = a[2];
        if (lane == 0) sE[1] = E;
    }

    __syncthreads();

    // combine (warp 0): P = <alpha_127, g_128> * 2^(Ef+Eb)
    if (fwd) {
        float dot = sA[s0]     * sG[s0]
                  + sA[s0 + 1] * sG[s0 + 1]
                  + sA[s0 + 2] * sG[s0 + 2];
        #pragma unroll
        for (int o = 16; o > 0; o >>= 1) dot += __shfl_xor_sync(FULL, dot, o);

        if (lane == 0) {
            float nll = -(logf(dot) + (float)(sE[0] + sE[1]) * LN2);
            if (!isfinite(nll) || nll >= 1e29f) nll = 0.0f;
            int denom = tl > 0 ? tl : 1;
            g_per_n[n] = nll / (float)denom;
        }
    }

    // last-block-done finalize (non-blocking, single-writer fence pattern)
    __syncthreads();
    if (tid == 0) {
        __threadfence();
        unsigned old = atomicAdd(&g_blkdone, 1u);
        if (old == (unsigned)(gridDim.x - 1)) {
            __threadfence();
            float acc = 0.0f;
            #pragma unroll
            for (int i = 0; i < N_; i++) acc += ldcg_f(g_per_n + i);
            out[0] = acc / (float)N_;
            g_blkdone = 0u;
        }
    }
}

extern "C" void kernel_launch(void* const* d_in, const int* in_sizes, int n_in,
                              void* d_out, int out_size)
{
    const float* preds          = (const float*)d_in[0];
    const int*   targets        = (const int*)d_in[1];
    const int*   pred_lengths   = (const int*)d_in[2];
    const int*   target_lengths = (const int*)d_in[3];
    float* out = (float*)d_out;

    lse_gather_kernel<<<T_ * N_, 256>>>(preds, targets);
    ctc_forward_kernel<<<N_, 64>>>(targets, pred_lengths, target_lengths, out);
}